// round 10
// baseline (speedup 1.0000x reference)
#include <cuda_runtime.h>

#define SEQ   600
#define BATCH 4096
#define INP   6
#define HID   30
#define OUTD  61
#define VLEN  36              // x(6) + h(30)
#define NTHR  256             // 8 warps
#define WPB   8               // warps per block
#define BPW   4               // batches per warp
#define BBLK  (WPB * BPW)     // 32 batches per block
#define NBLK  (BATCH / BBLK)  // 128 blocks

typedef unsigned long long ull;

// ---------------- preprocessed weights (device globals) ----------------
__device__ __align__(16) float g_W[4][32][VLEN];  // [gate][unit][ x(6) | h(30) ]
__device__ float g_bias[4][32];                   // b_ih + b_hh (0 for pad units)
__device__ float g_M[HID][OUTD];                  // fused fc1+fc2
__device__ float g_bv[OUTD];                      // b2 + b1 @ W2^T

// ---------------- helpers ----------------
__device__ __forceinline__ void ffma2(ull& acc, ull a, ull b) {
    asm("fma.rn.f32x2 %0, %1, %2, %0;" : "+l"(acc) : "l"(a), "l"(b));
}
__device__ __forceinline__ ull pack2(float x, float y) {
    ull r; asm("mov.b64 %0, {%1, %2};" : "=l"(r) : "f"(x), "f"(y)); return r;
}
__device__ __forceinline__ float hsum2(ull v) {
    float2 r; asm("mov.b64 {%0, %1}, %2;" : "=f"(r.x), "=f"(r.y) : "l"(v));
    return r.x + r.y;
}
__device__ __forceinline__ float tanh_fast(float x) {
    float r; asm("tanh.approx.f32 %0, %1;" : "=f"(r) : "f"(x)); return r;
}
__device__ __forceinline__ float sigmoid_fast(float x) {
    return fmaf(0.5f, tanh_fast(0.5f * x), 0.5f);
}

// ---------------- prep kernel ----------------
__global__ void prep_kernel(const float* __restrict__ Wih, const float* __restrict__ Whh,
                            const float* __restrict__ bih, const float* __restrict__ bhh,
                            const float* __restrict__ W1,  const float* __restrict__ b1,
                            const float* __restrict__ W2,  const float* __restrict__ b2) {
    int tid = threadIdx.x;
    for (int idx = tid; idx < 4 * 32 * VLEN; idx += blockDim.x) {
        int g = idx / (32 * VLEN);
        int r = idx % (32 * VLEN);
        int u = r / VLEN, j = r % VLEN;
        float w = 0.0f;
        if (u < HID) {
            if (j < INP) w = Wih[(g * HID + u) * INP + j];
            else         w = Whh[(g * HID + u) * HID + (j - INP)];
        }
        g_W[g][u][j] = w;
    }
    for (int idx = tid; idx < 4 * 32; idx += blockDim.x) {
        int g = idx / 32, u = idx % 32;
        g_bias[g][u] = (u < HID) ? (bih[g * HID + u] + bhh[g * HID + u]) : 0.0f;
    }
    for (int idx = tid; idx < HID * OUTD; idx += blockDim.x) {
        int j = idx / OUTD, o = idx % OUTD;
        float s = 0.0f;
        for (int k = 0; k < HID; k++) s += W1[k * HID + j] * W2[o * HID + k];
        g_M[j][o] = s;
    }
    for (int o = tid; o < OUTD; o += blockDim.x) {
        float s = b2[o];
        for (int k = 0; k < HID; k++) s += b1[k] * W2[o * HID + k];
        g_bv[o] = s;
    }
}

// ---------------- main persistent LSTM kernel (warp-autonomous, anti-phase) ----------------
__global__ void __launch_bounds__(NTHR, 1)
lstm_kernel(const float* __restrict__ X, float* __restrict__ out) {
    __shared__ __align__(16) float hb[2][WPB][BPW][32];   // 8192 B, h double-buffered
    __shared__ __align__(16) float xb[WPB][2][BPW * INP]; // 1536 B, x double-buffered

    const int tid    = threadIdx.x;
    const int lane   = tid & 31;                 // unit 0..31 (30 real, 2 pad)
    const int wid    = tid >> 5;                 // warp 0..7 ; SMSP = wid & 3
    const int bfirst = (blockIdx.x * WPB + wid) * BPW;
    const bool xlane = (lane < BPW * INP / 4);   // lanes 0..5 stage x

    // ---- weights for (all 4 gates, unit=lane): 4 x 18 ull = 144 regs ----
    ull w[4][18];
    ull bias2[4];
#pragma unroll
    for (int g = 0; g < 4; g++) {
        const ull* wp = (const ull*)&g_W[g][lane][0];
#pragma unroll
        for (int k = 0; k < 18; k++) w[g][k] = wp[k];
        bias2[g] = pack2(g_bias[g][lane], 0.0f);
    }

    // ---- init: zero h buf 0, stage x(0) ----
#pragma unroll
    for (int b = 0; b < BPW; b++) hb[0][wid][b][lane] = 0.0f;
    if (xlane) {
        const float4 v = *(const float4*)(X + (size_t)bfirst * INP + lane * 4);
        *(float4*)&xb[wid][0][lane * 4] = v;
    }
    __syncwarp();

    // ---- anti-phase stagger: second warp on each SMSP (wid 4..7) delays ~300 cyc
    // so its ACT phase overlaps the partner warp's MAC phase for all 600 steps.
    if (wid & 4) {
        float z = 1.0f;
#pragma unroll
        for (int k = 0; k < 75; k++)
            asm volatile("add.f32 %0, %0, 0f00000000;" : "+f"(z));  // dependent, lat 4 each
        asm volatile("" :: "f"(z));  // keep
    }

    float c[BPW] = {0.0f, 0.0f, 0.0f, 0.0f};

    int cur = 0;
#pragma unroll 1
    for (int t = 0; t < SEQ; ++t) {
        // prefetch x(t+1) into registers (clamped at end; value unused then)
        float4 xp;
        const int tn = (t + 1 < SEQ) ? t + 1 : t;
        if (xlane)
            xp = *(const float4*)(X + ((size_t)tn * BATCH + bfirst) * INP + lane * 4);

        const float* xr = &xb[wid][t & 1][0];

        // ===== Phase 1: all MACs, all batches (LDS only; no STS) =====
        ull acc[BPW][4];
#pragma unroll
        for (int b = 0; b < BPW; b++) {
            ull a0 = bias2[0], a1 = bias2[1], a2 = bias2[2], a3 = bias2[3];
            ull vx0 = *(const ull*)(xr + 6 * b);
            ull vx1 = *(const ull*)(xr + 6 * b + 2);
            ull vx2 = *(const ull*)(xr + 6 * b + 4);
            ffma2(a0, w[0][0], vx0); ffma2(a1, w[1][0], vx0);
            ffma2(a2, w[2][0], vx0); ffma2(a3, w[3][0], vx0);
            ffma2(a0, w[0][1], vx1); ffma2(a1, w[1][1], vx1);
            ffma2(a2, w[2][1], vx1); ffma2(a3, w[3][1], vx1);
            ffma2(a0, w[0][2], vx2); ffma2(a1, w[1][2], vx2);
            ffma2(a2, w[2][2], vx2); ffma2(a3, w[3][2], vx2);
            const float* hrow = &hb[cur][wid][b][0];
            const ulonglong2* h2 = (const ulonglong2*)hrow;
#pragma unroll
            for (int k = 0; k < 7; k++) {
                ulonglong2 vh = h2[k];
                ffma2(a0, w[0][3 + 2 * k], vh.x); ffma2(a1, w[1][3 + 2 * k], vh.x);
                ffma2(a2, w[2][3 + 2 * k], vh.x); ffma2(a3, w[3][3 + 2 * k], vh.x);
                ffma2(a0, w[0][4 + 2 * k], vh.y); ffma2(a1, w[1][4 + 2 * k], vh.y);
                ffma2(a2, w[2][4 + 2 * k], vh.y); ffma2(a3, w[3][4 + 2 * k], vh.y);
            }
            ull vhl = *(const ull*)(hrow + 28);
            ffma2(a0, w[0][17], vhl); ffma2(a1, w[1][17], vhl);
            ffma2(a2, w[2][17], vhl); ffma2(a3, w[3][17], vhl);
            acc[b][0] = a0; acc[b][1] = a1; acc[b][2] = a2; acc[b][3] = a3;
        }

        // publish x(t+1) now (before the ACT tail; made visible by step-end syncwarp)
        if (xlane) *(float4*)&xb[wid][(t + 1) & 1][lane * 4] = xp;

        // ===== Phase 2: activations + state updates; store each h when ready =====
        float* hn = &hb[cur ^ 1][wid][0][0];
#pragma unroll
        for (int b = 0; b < BPW; b++) {
            float si = sigmoid_fast(hsum2(acc[b][0]));
            float sf = sigmoid_fast(hsum2(acc[b][1]));
            float tg = tanh_fast   (hsum2(acc[b][2]));
            float so = sigmoid_fast(hsum2(acc[b][3]));
            c[b] = fmaf(sf, c[b], si * tg);
            hn[b * 32 + lane] = so * tanh_fast(c[b]);   // pad lanes write 0 naturally
        }

        __syncwarp();   // cross-lane visibility of h(t) and x(t+1)
        cur ^= 1;
    }

    // ---- fused fc1+fc2 epilogue over the block's 32 batches ----
    __syncthreads();
    for (int idx = tid; idx < BBLK * OUTD; idx += NTHR) {
        int lb = idx / OUTD, o = idx % OUTD;
        int ww = lb / BPW, b = lb % BPW;
        float s = g_bv[o];
#pragma unroll
        for (int j = 0; j < HID; j++) s += hb[cur][ww][b][j] * g_M[j][o];
        out[(size_t)(blockIdx.x * BBLK + lb) * OUTD + o] = s;
    }
}

// ---------------- launch ----------------
extern "C" void kernel_launch(void* const* d_in, const int* in_sizes, int n_in,
                              void* d_out, int out_size) {
    const float* X   = (const float*)d_in[0];
    const float* Wih = (const float*)d_in[1];
    const float* Whh = (const float*)d_in[2];
    const float* bih = (const float*)d_in[3];
    const float* bhh = (const float*)d_in[4];
    const float* W1  = (const float*)d_in[5];
    const float* b1  = (const float*)d_in[6];
    const float* W2  = (const float*)d_in[7];
    const float* b2  = (const float*)d_in[8];

    prep_kernel<<<1, 256>>>(Wih, Whh, bih, bhh, W1, b1, W2, b2);
    lstm_kernel<<<NBLK, NTHR>>>(X, (float*)d_out);
}

// round 11
// speedup vs baseline: 1.0939x; 1.0939x over previous
#include <cuda_runtime.h>

#define SEQ   600
#define BATCH 4096
#define INP   6
#define HID   30
#define OUTD  61
#define VLEN  36              // x(6) + h(30)
#define NTHR  256             // 8 warps
#define WPB   8               // warps per block
#define BPW   4               // batches per warp
#define BBLK  (WPB * BPW)     // 32 batches per block
#define NBLK  (BATCH / BBLK)  // 128 blocks

typedef unsigned long long ull;

// ---------------- preprocessed weights (device globals) ----------------
__device__ __align__(16) float g_W[4][32][VLEN];  // [gate][unit][ x(6) | h(30) ]
__device__ float g_bias[4][32];                   // b_ih + b_hh (0 for pad units)
__device__ float g_M[HID][OUTD];                  // fused fc1+fc2
__device__ float g_bv[OUTD];                      // b2 + b1 @ W2^T

// ---------------- helpers ----------------
__device__ __forceinline__ void ffma2(ull& acc, ull a, ull b) {
    asm("fma.rn.f32x2 %0, %1, %2, %0;" : "+l"(acc) : "l"(a), "l"(b));
}
__device__ __forceinline__ ull pack2(float x, float y) {
    ull r; asm("mov.b64 %0, {%1, %2};" : "=l"(r) : "f"(x), "f"(y)); return r;
}
__device__ __forceinline__ float hsum2(ull v) {
    float2 r; asm("mov.b64 {%0, %1}, %2;" : "=f"(r.x), "=f"(r.y) : "l"(v));
    return r.x + r.y;
}
__device__ __forceinline__ float tanh_fast(float x) {
    float r; asm("tanh.approx.f32 %0, %1;" : "=f"(r) : "f"(x)); return r;
}
__device__ __forceinline__ float sigmoid_fast(float x) {
    return fmaf(0.5f, tanh_fast(0.5f * x), 0.5f);
}

// ---------------- prep kernel ----------------
__global__ void prep_kernel(const float* __restrict__ Wih, const float* __restrict__ Whh,
                            const float* __restrict__ bih, const float* __restrict__ bhh,
                            const float* __restrict__ W1,  const float* __restrict__ b1,
                            const float* __restrict__ W2,  const float* __restrict__ b2) {
    int tid = threadIdx.x;
    for (int idx = tid; idx < 4 * 32 * VLEN; idx += blockDim.x) {
        int g = idx / (32 * VLEN);
        int r = idx % (32 * VLEN);
        int u = r / VLEN, j = r % VLEN;
        float w = 0.0f;
        if (u < HID) {
            if (j < INP) w = Wih[(g * HID + u) * INP + j];
            else         w = Whh[(g * HID + u) * HID + (j - INP)];
        }
        g_W[g][u][j] = w;
    }
    for (int idx = tid; idx < 4 * 32; idx += blockDim.x) {
        int g = idx / 32, u = idx % 32;
        g_bias[g][u] = (u < HID) ? (bih[g * HID + u] + bhh[g * HID + u]) : 0.0f;
    }
    for (int idx = tid; idx < HID * OUTD; idx += blockDim.x) {
        int j = idx / OUTD, o = idx % OUTD;
        float s = 0.0f;
        for (int k = 0; k < HID; k++) s += W1[k * HID + j] * W2[o * HID + k];
        g_M[j][o] = s;
    }
    for (int o = tid; o < OUTD; o += blockDim.x) {
        float s = b2[o];
        for (int k = 0; k < HID; k++) s += b1[k] * W2[o * HID + k];
        g_bv[o] = s;
    }
}

// load one batch's v = [x(3 ull) | h(15 ull)] into 18 ull regs
__device__ __forceinline__ void load_v(const float* __restrict__ xr,
                                       const float* __restrict__ hrow, ull* v) {
    v[0] = *(const ull*)(xr);
    v[1] = *(const ull*)(xr + 2);
    v[2] = *(const ull*)(xr + 4);
    const ulonglong2* h2 = (const ulonglong2*)hrow;
#pragma unroll
    for (int k = 0; k < 7; k++) { ulonglong2 t = h2[k]; v[3 + 2 * k] = t.x; v[4 + 2 * k] = t.y; }
    v[17] = *(const ull*)(hrow + 28);
}

// 4-gate MAC for a BATCH PAIR, interleaved so consecutive FFMA2 share w[g][k]
// (multiplier-slot operand reuse -> breaks the 3-distinct-bank rt penalty)
__device__ __forceinline__ void mac_pair(const ull w[4][18], const ull bias2[4],
                                         const ull* v0, const ull* v1,
                                         ull* acc0 /*[4]*/, ull* acc1 /*[4]*/) {
    ull a00 = bias2[0], a01 = bias2[1], a02 = bias2[2], a03 = bias2[3];
    ull a10 = bias2[0], a11 = bias2[1], a12 = bias2[2], a13 = bias2[3];
#pragma unroll
    for (int k = 0; k < 18; k++) {
        ull u0 = v0[k], u1 = v1[k];
        ffma2(a00, w[0][k], u0); ffma2(a10, w[0][k], u1);   // w[0][k] shared
        ffma2(a01, w[1][k], u0); ffma2(a11, w[1][k], u1);   // w[1][k] shared
        ffma2(a02, w[2][k], u0); ffma2(a12, w[2][k], u1);   // w[2][k] shared
        ffma2(a03, w[3][k], u0); ffma2(a13, w[3][k], u1);   // w[3][k] shared
    }
    acc0[0] = a00; acc0[1] = a01; acc0[2] = a02; acc0[3] = a03;
    acc1[0] = a10; acc1[1] = a11; acc1[2] = a12; acc1[3] = a13;
}

// activation + state update for one batch
__device__ __forceinline__ float act_batch(const ull* acc, float& c) {
    float si = sigmoid_fast(hsum2(acc[0]));
    float sf = sigmoid_fast(hsum2(acc[1]));
    float tg = tanh_fast   (hsum2(acc[2]));
    float so = sigmoid_fast(hsum2(acc[3]));
    c = fmaf(sf, c, si * tg);
    return so * tanh_fast(c);
}

// ---------------- main persistent LSTM kernel ----------------
__global__ void __launch_bounds__(NTHR, 1)
lstm_kernel(const float* __restrict__ X, float* __restrict__ out) {
    __shared__ __align__(16) float hb[2][WPB][BPW][32];   // 8192 B, h double-buffered
    __shared__ __align__(16) float xb[WPB][2][BPW * INP]; // 1536 B, x double-buffered

    const int tid    = threadIdx.x;
    const int lane   = tid & 31;                 // unit 0..31 (30 real, 2 pad)
    const int wid    = tid >> 5;                 // warp 0..7
    const int bfirst = (blockIdx.x * WPB + wid) * BPW;
    const bool xlane = (lane < BPW * INP / 4);   // lanes 0..5 stage x

    // ---- weights for (all 4 gates, unit=lane): 4 x 18 ull = 144 regs ----
    ull w[4][18];
    ull bias2[4];
#pragma unroll
    for (int g = 0; g < 4; g++) {
        const ull* wp = (const ull*)&g_W[g][lane][0];
#pragma unroll
        for (int k = 0; k < 18; k++) w[g][k] = wp[k];
        bias2[g] = pack2(g_bias[g][lane], 0.0f);
    }

    // ---- init ----
#pragma unroll
    for (int b = 0; b < BPW; b++) hb[0][wid][b][lane] = 0.0f;
    if (xlane) {
        const float4 v = *(const float4*)(X + (size_t)bfirst * INP + lane * 4);
        *(float4*)&xb[wid][0][lane * 4] = v;
    }
    __syncwarp();

    float c[BPW] = {0.0f, 0.0f, 0.0f, 0.0f};

    int cur = 0;
#pragma unroll 1
    for (int t = 0; t < SEQ; ++t) {
        // prefetch x(t+1)
        float4 xp;
        const int tn = (t + 1 < SEQ) ? t + 1 : t;
        if (xlane)
            xp = *(const float4*)(X + ((size_t)tn * BATCH + bfirst) * INP + lane * 4);

        const float* xr = &xb[wid][t & 1][0];
        const float* hc = &hb[cur][wid][0][0];
        float*       hn = &hb[cur ^ 1][wid][0][0];

        // ===== stage A: load + MAC batches 0,1 (w-shared interleave) =====
        ull vA0[18], vA1[18];
        load_v(xr + 0 * INP, hc + 0 * 32, vA0);
        load_v(xr + 1 * INP, hc + 1 * 32, vA1);
        ull accA0[4], accA1[4];
        mac_pair(w, bias2, vA0, vA1, accA0, accA1);

        // hoist stage-B loads BEFORE any STS (aliasing would block later LDS)
        ull vB0[18], vB1[18];
        load_v(xr + 2 * INP, hc + 2 * 32, vB0);
        load_v(xr + 3 * INP, hc + 3 * 32, vB1);

        // stage-A activations + stores (overlap with stage-B MACs below)
        float h0 = act_batch(accA0, c[0]);
        float h1 = act_batch(accA1, c[1]);
        hn[0 * 32 + lane] = h0;
        hn[1 * 32 + lane] = h1;

        // ===== stage B: MAC batches 2,3 then activate =====
        ull accB0[4], accB1[4];
        mac_pair(w, bias2, vB0, vB1, accB0, accB1);
        float h2 = act_batch(accB0, c[2]);
        float h3 = act_batch(accB1, c[3]);
        hn[2 * 32 + lane] = h2;
        hn[3 * 32 + lane] = h3;

        // publish x(t+1)
        if (xlane) *(float4*)&xb[wid][(t + 1) & 1][lane * 4] = xp;
        __syncwarp();
        cur ^= 1;
    }

    // ---- fused fc1+fc2 epilogue over the block's 32 batches ----
    __syncthreads();
    for (int idx = tid; idx < BBLK * OUTD; idx += NTHR) {
        int lb = idx / OUTD, o = idx % OUTD;
        int ww = lb / BPW, b = lb % BPW;
        float s = g_bv[o];
#pragma unroll
        for (int j = 0; j < HID; j++) s += hb[cur][ww][b][j] * g_M[j][o];
        out[(size_t)(blockIdx.x * BBLK + lb) * OUTD + o] = s;
    }
}

// ---------------- launch ----------------
extern "C" void kernel_launch(void* const* d_in, const int* in_sizes, int n_in,
                              void* d_out, int out_size) {
    const float* X   = (const float*)d_in[0];
    const float* Wih = (const float*)d_in[1];
    const float* Whh = (const float*)d_in[2];
    const float* bih = (const float*)d_in[3];
    const float* bhh = (const float*)d_in[4];
    const float* W1  = (const float*)d_in[5];
    const float* b1  = (const float*)d_in[6];
    const float* W2  = (const float*)d_in[7];
    const float* b2  = (const float*)d_in[8];

    prep_kernel<<<1, 256>>>(Wih, Whh, bih, bhh, W1, b1, W2, b2);
    lstm_kernel<<<NBLK, NTHR>>>(X, (float*)d_out);
}

// round 13
// speedup vs baseline: 1.2111x; 1.1072x over previous
#include <cuda_runtime.h>
#include <cuda_bf16.h>
#include <cstdint>

#define SEQ   600
#define BATCH 4096
#define INP   6
#define HID   30
#define OUTD  61
#define NB    32               // batches per CTA (GEMM M)
#define NBLK  (BATCH / NB)     // 128 CTAs
#define NTHR  256              // 8 warps
#define BST   104              // v-row byte stride in sB (bank-spread, 8B mult)
#define SBB   (NB * BST)       // 3328 B per (buf, term)

typedef unsigned long long ull;
typedef uint32_t u32;

// ---------------- device globals ----------------
// weight B-fragments: [warp][ntile][ktile][term][lane][j]  (j: b0/b1)
__device__ u32  g_Bfrag[8][2][3][2][32][2];
__device__ float g_M[HID][OUTD];     // fused fc1+fc2
__device__ float g_bv[OUTD];

// ---------------- helpers ----------------
__device__ __forceinline__ float tanh_fast(float x) {
    float r; asm("tanh.approx.f32 %0, %1;" : "=f"(r) : "f"(x)); return r;
}
__device__ __forceinline__ float sigmoid_fast(float x) {
    return fmaf(0.5f, tanh_fast(0.5f * x), 0.5f);
}
__device__ __forceinline__ u32 pack_bf16x2(float lo_k, float hi_k) {
    __nv_bfloat162 p = __floats2bfloat162_rn(lo_k, hi_k);   // .x = first elem (lower k)
    return *(u32*)&p;
}
// byte offset of k-value within one batch's v-row (slot layout: one ull slot
// s = kt*4+tig holds pairs (p, p+4) where p = k/2 -> LDS.64 = one A-frag reg pair)
__device__ __host__ __forceinline__ u32 koff(int k) {
    int p = k >> 1, kt = p >> 3, q = p & 7;
    return (u32)(((kt << 2) + (q & 3)) * 8 + (q >> 2) * 4 + (k & 1) * 2);
}

__device__ __forceinline__ void mma16816(float* d, const u32* a, const u32* b) {
    asm volatile(
        "mma.sync.aligned.m16n8k16.row.col.f32.bf16.bf16.f32 "
        "{%0,%1,%2,%3}, {%4,%5,%6,%7}, {%8,%9}, {%0,%1,%2,%3};"
        : "+f"(d[0]), "+f"(d[1]), "+f"(d[2]), "+f"(d[3])
        : "r"(a[0]), "r"(a[1]), "r"(a[2]), "r"(a[3]), "r"(b[0]), "r"(b[1]));
}

// ---------------- prep kernel ----------------
__device__ __forceinline__ float Wval(const float* Wih, const float* Whh,
                                      const float* bih, const float* bhh, int r, int k) {
    int u = r >> 2, g = r & 3;
    if (u >= HID) return 0.0f;
    if (k < HID)       return Whh[(g * HID + u) * HID + k];
    if (k < HID + INP) return Wih[(g * HID + u) * INP + (k - HID)];
    if (k == 36)       return bih[g * HID + u] + bhh[g * HID + u];
    return 0.0f;
}

__global__ void prep_kernel(const float* __restrict__ Wih, const float* __restrict__ Whh,
                            const float* __restrict__ bih, const float* __restrict__ bhh,
                            const float* __restrict__ W1,  const float* __restrict__ b1,
                            const float* __restrict__ W2,  const float* __restrict__ b2) {
    int tid = threadIdx.x;
    // B fragments: b_j holds k = 2*tig + 16*kt + 8*j + {0,1}, col(gate-row) = 16w+8nt+g0
    for (int idx = tid; idx < 8 * 2 * 3 * 2 * 32 * 2; idx += blockDim.x) {
        int j    = idx & 1;
        int lane = (idx >> 1) & 31;
        int tm   = (idx >> 6) & 1;
        int kt   = (idx >> 7) % 3;
        int nt   = (idx >> 7) / 3 & 1;
        int w    = idx / (2 * 3 * 2 * 32 * 2);
        int g0 = lane >> 2, tig = lane & 3;
        int r = 16 * w + 8 * nt + g0;
        int k = 2 * tig + 16 * kt + 8 * j;
        float w0 = Wval(Wih, Whh, bih, bhh, r, k);
        float w1 = Wval(Wih, Whh, bih, bhh, r, k + 1);
        float h0 = __bfloat162float(__float2bfloat16(w0));
        float h1 = __bfloat162float(__float2bfloat16(w1));
        u32 v = (tm == 0) ? pack_bf16x2(h0, h1) : pack_bf16x2(w0 - h0, w1 - h1);
        g_Bfrag[w][nt][kt][tm][lane][j] = v;
    }
    for (int idx = tid; idx < HID * OUTD; idx += blockDim.x) {
        int j = idx / OUTD, o = idx % OUTD;
        float s = 0.0f;
        for (int kk = 0; kk < HID; kk++) s += W1[kk * HID + j] * W2[o * HID + kk];
        g_M[j][o] = s;
    }
    for (int o = tid; o < OUTD; o += blockDim.x) {
        float s = b2[o];
        for (int kk = 0; kk < HID; kk++) s += b1[kk] * W2[o * HID + kk];
        g_bv[o] = s;
    }
}

// ---------------- main kernel: 3xBF16 mma.sync recurrence ----------------
__global__ void __launch_bounds__(NTHR, 1)
lstm_kernel(const float* __restrict__ X, float* __restrict__ out) {
    // v = [h|x|bias] as bf16, hi/lo terms, double-buffered
    __shared__ __align__(16) char sB[2][2][SBB];   // 13312 B

    const int tid   = threadIdx.x;
    const int lane  = tid & 31;
    const int wid   = tid >> 5;            // 0..7 : owns gate-rows 16w..16w+15
    const int g0    = lane >> 2;
    const int tig   = lane & 3;
    const int bbase = blockIdx.x * NB;

    // persistent weight fragments
    u32 Bf[2][3][2][2];
#pragma unroll
    for (int nt = 0; nt < 2; nt++)
#pragma unroll
        for (int kt = 0; kt < 3; kt++)
#pragma unroll
            for (int tm = 0; tm < 2; tm++) {
                Bf[nt][kt][tm][0] = g_Bfrag[wid][nt][kt][tm][lane][0];
                Bf[nt][kt][tm][1] = g_Bfrag[wid][nt][kt][tm][lane][1];
            }

    // init: zero both buffers, set bias col (k=36 -> byte 80) in hi term
    for (int i = tid; i < 2 * 2 * SBB / 4; i += NTHR) ((u32*)sB)[i] = 0u;
    __syncthreads();
    if (tid < NB) {
        *(u32*)(&sB[0][0][tid * BST + 80]) = 0x00003F80u;   // {bf16(1.0), 0}
        *(u32*)(&sB[1][0][tid * BST + 80]) = 0x00003F80u;
    }
    // stage x(0) into buf 0
    const int bx = tid & 31, jx = tid >> 5;   // tid<96: batch bx, x-pair jx
    if (tid < 96) {
        float2 xv = *(const float2*)(X + ((size_t)bbase + bx) * INP + 2 * jx);
        float h0 = __bfloat162float(__float2bfloat16(xv.x));
        float h1 = __bfloat162float(__float2bfloat16(xv.y));
        *(u32*)(&sB[0][0][bx * BST + koff(30 + 2 * jx)]) = pack_bf16x2(h0, h1);
        *(u32*)(&sB[0][1][bx * BST + koff(30 + 2 * jx)]) = pack_bf16x2(xv.x - h0, xv.y - h1);
    }
    __syncthreads();

    // per-lane epilogue identity: tile-pair (dm, nt) -> unit / batch
    const int myu = 4 * wid + (tig >> 1);     // + 2*nt
    const int myb0 = g0 + 8 * (tig & 1);      // + 16*dm
    const int odd = tig & 1;

    float cst[4] = {0.0f, 0.0f, 0.0f, 0.0f};

#pragma unroll 1
    for (int t = 0; t < SEQ; ++t) {
        const int bt = t & 1, nb = bt ^ 1;

        // prefetch x(t+1)
        float2 xv = make_float2(0.0f, 0.0f);
        const int tn = (t + 1 < SEQ) ? t + 1 : t;
        if (tid < 96)
            xv = *(const float2*)(X + ((size_t)tn * BATCH + bbase + bx) * INP + 2 * jx);

        // ---- load A fragments (v) from sB: one LDS.64 = {a_klo, a_khi} ----
        u32 A[2][3][2][4];
#pragma unroll
        for (int dm = 0; dm < 2; dm++)
#pragma unroll
            for (int kt = 0; kt < 3; kt++)
#pragma unroll
                for (int tm = 0; tm < 2; tm++) {
                    const char* base = sB[bt][tm];
                    ull v0 = *(const ull*)(base + (16 * dm + g0) * BST + (kt * 4 + tig) * 8);
                    ull v1 = *(const ull*)(base + (16 * dm + g0 + 8) * BST + (kt * 4 + tig) * 8);
                    A[dm][kt][tm][0] = (u32)v0;  A[dm][kt][tm][2] = (u32)(v0 >> 32);
                    A[dm][kt][tm][1] = (u32)v1;  A[dm][kt][tm][3] = (u32)(v1 >> 32);
                }

        // ---- 36 mma: 4 independent D tiles x 9 (3 kt x 3 terms) ----
        float D[2][2][4];
#pragma unroll
        for (int dm = 0; dm < 2; dm++)
#pragma unroll
            for (int nt = 0; nt < 2; nt++) {
                D[dm][nt][0] = D[dm][nt][1] = D[dm][nt][2] = D[dm][nt][3] = 0.0f;
#pragma unroll
                for (int kt = 0; kt < 3; kt++) {
                    mma16816(D[dm][nt], A[dm][kt][0], Bf[nt][kt][0]);  // vhi*whi
                    mma16816(D[dm][nt], A[dm][kt][0], Bf[nt][kt][1]);  // vhi*wlo
                    mma16816(D[dm][nt], A[dm][kt][1], Bf[nt][kt][0]);  // vlo*whi
                }
            }

        // ---- epilogue: gates via shfl.xor(1), act, c/h update, h store ----
#pragma unroll
        for (int dm = 0; dm < 2; dm++)
#pragma unroll
            for (int nt = 0; nt < 2; nt++) {
                float d0 = D[dm][nt][0], d1 = D[dm][nt][1];
                float d2 = D[dm][nt][2], d3 = D[dm][nt][3];
                float s0 = __shfl_xor_sync(0xffffffffu, d0, 1);
                float s1 = __shfl_xor_sync(0xffffffffu, d1, 1);
                float s2 = __shfl_xor_sync(0xffffffffu, d2, 1);
                float s3 = __shfl_xor_sync(0xffffffffu, d3, 1);
                // even tig: own (i,f) b=g0 in d0,d1; partner's (g,o) in s0,s1
                // odd  tig: own (g,o) b=g0+8 in d2,d3; partner's (i,f) in s2,s3
                float gi = odd ? s2 : d0;
                float gf = odd ? s3 : d1;
                float gg = odd ? d2 : s0;
                float go = odd ? d3 : s1;
                int st = dm * 2 + nt;
                float si = sigmoid_fast(gi);
                float sf = sigmoid_fast(gf);
                float tg = tanh_fast(gg);
                float so = sigmoid_fast(go);
                cst[st] = fmaf(sf, cst[st], si * tg);
                float h = so * tanh_fast(cst[st]);
                int u = myu + 2 * nt;
                int b = myb0 + 16 * dm;
                if (u < HID) {
                    float hh = __bfloat162float(__float2bfloat16(h));
                    *(__nv_bfloat16*)(&sB[nb][0][b * BST + koff(u)]) = __float2bfloat16(h);
                    *(__nv_bfloat16*)(&sB[nb][1][b * BST + koff(u)]) = __float2bfloat16(h - hh);
                }
            }

        // ---- publish x(t+1) into next buffer ----
        if (tid < 96) {
            float h0 = __bfloat162float(__float2bfloat16(xv.x));
            float h1 = __bfloat162float(__float2bfloat16(xv.y));
            *(u32*)(&sB[nb][0][bx * BST + koff(30 + 2 * jx)]) = pack_bf16x2(h0, h1);
            *(u32*)(&sB[nb][1][bx * BST + koff(30 + 2 * jx)]) = pack_bf16x2(xv.x - h0, xv.y - h1);
        }

        __syncthreads();
    }

    // ---- fused fc1+fc2 epilogue: h = hi + lo from final buffer (SEQ even -> buf 0) ----
    for (int idx = tid; idx < NB * OUTD; idx += NTHR) {
        int b = idx / OUTD, o = idx % OUTD;
        float s = g_bv[o];
#pragma unroll
        for (int j = 0; j < HID; j++) {
            float hv = __bfloat162float(*(__nv_bfloat16*)(&sB[0][0][b * BST + koff(j)]))
                     + __bfloat162float(*(__nv_bfloat16*)(&sB[0][1][b * BST + koff(j)]));
            s += hv * g_M[j][o];
        }
        out[(size_t)(bbase + b) * OUTD + o] = s;
    }
}

// ---------------- launch ----------------
extern "C" void kernel_launch(void* const* d_in, const int* in_sizes, int n_in,
                              void* d_out, int out_size) {
    const float* X   = (const float*)d_in[0];
    const float* Wih = (const float*)d_in[1];
    const float* Whh = (const float*)d_in[2];
    const float* bih = (const float*)d_in[3];
    const float* bhh = (const float*)d_in[4];
    const float* W1  = (const float*)d_in[5];
    const float* b1  = (const float*)d_in[6];
    const float* W2  = (const float*)d_in[7];
    const float* b2  = (const float*)d_in[8];

    prep_kernel<<<1, 256>>>(Wih, Whh, bih, bhh, W1, b1, W2, b2);
    lstm_kernel<<<NBLK, NTHR>>>(X, (float*)d_out);
}